// round 14
// baseline (speedup 1.0000x reference)
#include <cuda_runtime.h>
#include <cuda_bf16.h>
#include <math.h>
#include <stdint.h>

#define BATCH 2048
#define SEQ   128
#define HID   512
#define TOUT  24
#define NTHR  256    // 8 warps: 4 m-pairs x 2 n-halves
#define GRID  128
#define NKT   32

// ---- global scratch ----
__device__ uint4 g_Bpk[2][8][NKT][8][32];    // [enc/dec][slice][kt][ntl][lane]
__device__ uint4 g_A[16][2][8][NKT][2][32];  // [grp][plane][mt][kt][hi/lo][lane]
__device__ float g_xT[SEQ][BATCH];
__device__ float g_part[2][16][8][128];
__device__ unsigned g_flag[16][8][32];       // per-CTA publish counters (128B apart)
__device__ unsigned g_rst[16][32];

// ---- SMEM layout (bytes) ----
#define OFF_B    0         // 131072
#define OFF_EPE  131072
#define OFF_EPD  131584
#define OFF_FC2  132096
#define OFF_DINP 132352
#define OFF_RED  132864    // 2 x 128 floats
#define SMEM_SZ  133888

__device__ __forceinline__ uint32_t smem_u32(const void* p) {
    uint32_t a;
    asm("{ .reg .u64 t; cvta.to.shared.u64 t, %1; cvt.u32.u64 %0, t; }" : "=r"(a) : "l"(p));
    return a;
}
__device__ __forceinline__ void cpasync16(uint32_t dst, const void* src) {
    asm volatile("cp.async.cg.shared.global [%0], [%1], 16;" :: "r"(dst), "l"(src) : "memory");
}
__device__ __forceinline__ void cp_commit() { asm volatile("cp.async.commit_group;" ::: "memory"); }
__device__ __forceinline__ void cp_wait0()  { asm volatile("cp.async.wait_group 0;" ::: "memory"); }
__device__ __forceinline__ void mma_bf16(float* d, uint4 a, uint32_t b0, uint32_t b1) {
    asm volatile(
        "mma.sync.aligned.m16n8k16.row.col.f32.bf16.bf16.f32 "
        "{%0,%1,%2,%3}, {%4,%5,%6,%7}, {%8,%9}, {%0,%1,%2,%3};"
        : "+f"(d[0]), "+f"(d[1]), "+f"(d[2]), "+f"(d[3])
        : "r"(a.x), "r"(a.y), "r"(a.z), "r"(a.w), "r"(b0), "r"(b1));
}
__device__ __forceinline__ uint32_t pack_bf2(__nv_bfloat16 a, __nv_bfloat16 b) {
    __nv_bfloat162 t; t.x = a; t.y = b;
    return *reinterpret_cast<uint32_t*>(&t);
}
__device__ __forceinline__ void split2(float a, float b, uint32_t& hi, uint32_t& lo) {
    __nv_bfloat16 ah = __float2bfloat16(a);
    __nv_bfloat16 bh = __float2bfloat16(b);
    __nv_bfloat16 al = __float2bfloat16(a - __bfloat162float(ah));
    __nv_bfloat16 bl = __float2bfloat16(b - __bfloat162float(bh));
    hi = pack_bf2(ah, bh);
    lo = pack_bf2(al, bl);
}
__device__ __forceinline__ float ftanh(float x) {
    float e = __expf(2.0f * x);
    return 1.0f - __fdividef(2.0f, e + 1.0f);
}

// Prologue 1: pack Whh into fragment-ordered bf16 hi/lo.
__global__ void pack_b(const float* __restrict__ eW, const float* __restrict__ dW) {
    int e = blockIdx.x * 256 + threadIdx.x;
    const float* W = blockIdx.y ? dW : eW;
    uint4* dst = &g_Bpk[blockIdx.y][0][0][0][0];
    int lane = e & 31, ntl = (e >> 5) & 7, kt = (e >> 8) & 31, sl = e >> 13;
    int n = sl * 64 + ntl * 8 + (lane >> 2);
    int k = kt * 16 + 2 * (lane & 3);
    const float* r = W + n * HID + k;
    uint32_t b0h, b0l, b1h, b1l;
    split2(r[0], r[1], b0h, b0l);
    split2(r[8], r[9], b1h, b1l);
    dst[((sl * NKT + kt) * 8 + ntl) * 32 + lane] = make_uint4(b0h, b1h, b0l, b1l);
}

// Prologue 2: transpose x -> g_xT[s][b].
__global__ void transpose_x(const float* __restrict__ x) {
    __shared__ float tile[32][33];
    int bx = blockIdx.x * 32, sx = blockIdx.y * 32;
    int tx = threadIdx.x, ty = threadIdx.y;
    #pragma unroll
    for (int i = 0; i < 32; i += 8)
        tile[ty + i][tx] = x[(bx + ty + i) * SEQ + sx + tx];
    __syncthreads();
    #pragma unroll
    for (int i = 0; i < 32; i += 8)
        g_xT[sx + ty + i][bx + tx] = tile[tx][ty + i];
}

__global__ __launch_bounds__(NTHR, 1)
void rnn_kernel(const float* __restrict__ eWih,
                const float* __restrict__ ebih, const float* __restrict__ ebhh,
                const float* __restrict__ dWih,
                const float* __restrict__ dbih, const float* __restrict__ dbhh,
                const float* __restrict__ fcW, const float* __restrict__ fcb,
                float* __restrict__ out)
{
    extern __shared__ char smem[];
    const int tid  = threadIdx.x;
    const int wid  = tid >> 5, lane = tid & 31;
    const int gid  = lane >> 2, tig = lane & 3;
    const int g    = blockIdx.x >> 3, s = blockIdx.x & 7;
    const int b0   = g * 128, n0 = s * 64, s4 = s * 4;
    const int mp   = wid & 3, nhf = wid >> 2;
    const int mt0  = 2 * mp, mt1 = 2 * mp + 1;
    const int r00  = mt0 * 16 + gid, r01 = r00 + 8;
    const int r10  = mt1 * 16 + gid, r11 = r10 + 8;

    const uint4*   smB   = (const uint4*)(smem + OFF_B);
    const uint32_t smB_u = smem_u32(smem + OFF_B);
    float4* epE  = (float4*)(smem + OFF_EPE);
    float4* epD  = (float4*)(smem + OFF_EPD);
    float2* fc2  = (float2*)(smem + OFF_FC2);
    float*  dinp = (float*)(smem + OFF_DINP);
    float*  red  = (float*)(smem + OFF_RED);

    if (tid < 32) {
        int c0 = n0 + 2 * tid, c1 = c0 + 1;
        epE[tid] = make_float4(eWih[c0], eWih[c1],
                               ebih[c0] + ebhh[c0], ebih[c1] + ebhh[c1]);
        epD[tid] = make_float4(dWih[c0], dWih[c1],
                               dbih[c0] + dbhh[c0], dbih[c1] + dbhh[c1]);
        fc2[tid] = make_float2(fcW[c0], fcW[c1]);
    }
    const float fcb0 = fcb[0];

    // resident encoder B + zero FULL group plane-0
    {
        const uint4* bsrc = &g_Bpk[0][s][0][0][0];
        for (int i = tid; i < 8192; i += NTHR)
            cpasync16(smB_u + i * 16, bsrc + i);
        cp_commit();
        uint4* az = &g_A[g][0][0][0][0][0];
        for (int i = tid; i < 16384; i += NTHR) az[i] = make_uint4(0, 0, 0, 0);
    }
    cp_wait0();

    unsigned ph = 0;   // per-step publish target counter

    // publish: CTA-local sync (orders all warps' STGs), leader release + bump
    auto publish = [&]() {
        __syncthreads();
        if (tid == 0) {
            __threadfence();
            atomicAdd(&g_flag[g][s][0], 1u);
        }
    };

    publish();   // #1: zeros

    float acc[2][4][4];

    auto loadA = [&](uint4* S, const uint4* base, int kt) {
        const uint4* p0 = base + mt0 * 2048 + kt * 64 + lane;
        const uint4* p1 = base + mt1 * 2048 + kt * 64 + lane;
        S[0] = __ldcg(p0); S[1] = __ldcg(p0 + 32);
        S[2] = __ldcg(p1); S[3] = __ldcg(p1 + 32);
    };

    auto consume = [&](int kt, const uint4* S) {
        const uint4* bp = smB + kt * 256 + nhf * 128 + lane;
        uint4 b0 = bp[0], b1 = bp[32], b2 = bp[64], b3 = bp[96];
        mma_bf16(acc[0][0], S[0], b0.x, b0.y); mma_bf16(acc[1][0], S[2], b0.x, b0.y);
        mma_bf16(acc[0][1], S[0], b1.x, b1.y); mma_bf16(acc[1][1], S[2], b1.x, b1.y);
        mma_bf16(acc[0][2], S[0], b2.x, b2.y); mma_bf16(acc[1][2], S[2], b2.x, b2.y);
        mma_bf16(acc[0][3], S[0], b3.x, b3.y); mma_bf16(acc[1][3], S[2], b3.x, b3.y);
        mma_bf16(acc[0][0], S[1], b0.x, b0.y); mma_bf16(acc[1][0], S[3], b0.x, b0.y);
        mma_bf16(acc[0][1], S[1], b1.x, b1.y); mma_bf16(acc[1][1], S[3], b1.x, b1.y);
        mma_bf16(acc[0][2], S[1], b2.x, b2.y); mma_bf16(acc[1][2], S[3], b2.x, b2.y);
        mma_bf16(acc[0][3], S[1], b3.x, b3.y); mma_bf16(acc[1][3], S[3], b3.x, b3.y);
        mma_bf16(acc[0][0], S[0], b0.z, b0.w); mma_bf16(acc[1][0], S[2], b0.z, b0.w);
        mma_bf16(acc[0][1], S[0], b1.z, b1.w); mma_bf16(acc[1][1], S[2], b1.z, b1.w);
        mma_bf16(acc[0][2], S[0], b2.z, b2.w); mma_bf16(acc[1][2], S[2], b2.z, b2.w);
        mma_bf16(acc[0][3], S[0], b3.z, b3.w); mma_bf16(acc[1][3], S[2], b3.z, b3.w);
    };

    // kloop with distributed per-producer waits.
    auto kloop = [&](const uint4* base) {
        const unsigned tgt = ++ph;
        #pragma unroll
        for (int mi = 0; mi < 2; mi++)
            #pragma unroll
            for (int i = 0; i < 4; i++)
                #pragma unroll
                for (int j = 0; j < 4; j++) acc[mi][i][j] = 0.f;

        uint4 S0[4], S1[4];
        loadA(S0, base, s4);
        loadA(S1, base, s4 + 1);
        // snapshot all 8 producer flags (one LDG; overlapped with own consumes)
        unsigned fv = 0;
        if (lane < 8) fv = *(volatile const unsigned*)&g_flag[g][lane][0];
        consume(s4, S0);     loadA(S0, base, s4 + 2);
        consume(s4 + 1, S1); loadA(S1, base, s4 + 3);
        unsigned mask = __ballot_sync(0xffffffffu, (lane >= 8) || (fv >= tgt));
        consume(s4 + 2, S0);

        if ((mask & 0xffu) == 0xffu) {
            // fast path: all producers published -> continuous depth-2 pipeline
            loadA(S0, base, (s4 + 4) & 31);
            consume(s4 + 3, S1); loadA(S1, base, (s4 + 5) & 31);
            #pragma unroll 1
            for (int j = 0; j < 13; j++) {
                consume((s4 + 4 + 2 * j) & 31, S0); loadA(S0, base, (s4 + 6 + 2 * j) & 31);
                consume((s4 + 5 + 2 * j) & 31, S1); loadA(S1, base, (s4 + 7 + 2 * j) & 31);
            }
            consume((s4 + 30) & 31, S0);
            consume((s4 + 31) & 31, S1);
        } else {
            // slow path: per-producer just-in-time waits (rotated order)
            consume(s4 + 3, S1);
            #pragma unroll 1
            for (int j = 1; j < 8; j++) {
                const int p = (s + j) & 7;
                if (!((mask >> p) & 1u)) {
                    if (lane == 0) {
                        volatile const unsigned* fp = &g_flag[g][p][0];
                        while (*fp < tgt) { }
                        __threadfence();
                    }
                    __syncwarp();
                }
                const int kb = p * 4;
                loadA(S0, base, kb);     loadA(S1, base, kb + 1);
                consume(kb, S0);         loadA(S0, base, kb + 2);
                consume(kb + 1, S1);     loadA(S1, base, kb + 3);
                consume(kb + 2, S0);
                consume(kb + 3, S1);
            }
        }
    };

    auto epi = [&](float xa0, float xb0, float xa1, float xb1,
                   const float4* __restrict__ ep, uint4* __restrict__ gAw, bool dec) {
        float p00 = 0.f, p01 = 0.f, p10 = 0.f, p11 = 0.f;
        uint4 nh_[2][2], nl_[2][2];
        #pragma unroll
        for (int mi = 0; mi < 2; mi++) {
            float xva = mi ? xa1 : xa0;
            float xvb = mi ? xb1 : xb0;
            #pragma unroll
            for (int j = 0; j < 4; j++) {
                int pp = 16 * nhf + 4 * j + tig;
                float4 co = ep[pp];
                float h00 = ftanh(acc[mi][j][0] + xva * co.x + co.z);
                float h01 = ftanh(acc[mi][j][1] + xva * co.y + co.w);
                float h10 = ftanh(acc[mi][j][2] + xvb * co.x + co.z);
                float h11 = ftanh(acc[mi][j][3] + xvb * co.y + co.w);
                if (dec) {
                    float2 f = fc2[pp];
                    if (mi == 0) {
                        p00 = fmaf(h00, f.x, fmaf(h01, f.y, p00));
                        p01 = fmaf(h10, f.x, fmaf(h11, f.y, p01));
                    } else {
                        p10 = fmaf(h00, f.x, fmaf(h01, f.y, p10));
                        p11 = fmaf(h10, f.x, fmaf(h11, f.y, p11));
                    }
                }
                int ktl = j >> 1;
                if ((j & 1) == 0) {
                    split2(h00, h01, nh_[mi][ktl].x, nl_[mi][ktl].x);
                    split2(h10, h11, nh_[mi][ktl].y, nl_[mi][ktl].y);
                } else {
                    split2(h00, h01, nh_[mi][ktl].z, nl_[mi][ktl].z);
                    split2(h10, h11, nh_[mi][ktl].w, nl_[mi][ktl].w);
                }
            }
        }
        #pragma unroll
        for (int mi = 0; mi < 2; mi++) {
            int mt = 2 * mp + mi;
            #pragma unroll
            for (int ktl = 0; ktl < 2; ktl++) {
                int kt = s4 + 2 * nhf + ktl;
                gAw[mt * 2048 + kt * 64 + lane]      = nh_[mi][ktl];
                gAw[mt * 2048 + kt * 64 + 32 + lane] = nl_[mi][ktl];
            }
        }
        if (dec) {
            p00 += __shfl_xor_sync(0xffffffffu, p00, 1);
            p00 += __shfl_xor_sync(0xffffffffu, p00, 2);
            p01 += __shfl_xor_sync(0xffffffffu, p01, 1);
            p01 += __shfl_xor_sync(0xffffffffu, p01, 2);
            p10 += __shfl_xor_sync(0xffffffffu, p10, 1);
            p10 += __shfl_xor_sync(0xffffffffu, p10, 2);
            p11 += __shfl_xor_sync(0xffffffffu, p11, 1);
            p11 += __shfl_xor_sync(0xffffffffu, p11, 2);
            if (tig == 0) {
                red[nhf * 128 + r00] = p00;
                red[nhf * 128 + r01] = p01;
                red[nhf * 128 + r10] = p10;
                red[nhf * 128 + r11] = p11;
            }
        }
    };

    const uint4* gAr[2] = { &g_A[g][0][0][0][0][0], &g_A[g][1][0][0][0][0] };
    uint4*       gAw[2] = { &g_A[g][0][0][0][0][0], &g_A[g][1][0][0][0][0] };

    // ---- encoder: 128 steps ----
    #pragma unroll 1
    for (int t = 0; t < SEQ; t++) {
        const int pl = t & 1;
        float xa0 = __ldg(&g_xT[t][b0 + r00]);
        float xb0 = __ldg(&g_xT[t][b0 + r01]);
        float xa1 = __ldg(&g_xT[t][b0 + r10]);
        float xb1 = __ldg(&g_xT[t][b0 + r11]);
        kloop(gAr[pl]);
        epi(xa0, xb0, xa1, xb1, epE, gAw[1 - pl], false);
        publish();
    }

    // ---- swap to decoder B + init feedback input ----
    __syncthreads();
    {
        const uint4* bsrc = &g_Bpk[1][s][0][0][0];
        for (int i = tid; i < 8192; i += NTHR)
            cpasync16(smB_u + i * 16, bsrc + i);
        cp_commit();
    }
    if (tid < 128) dinp[tid] = __ldg(&g_xT[SEQ - 1][b0 + tid]);
    cp_wait0();
    __syncthreads();

    // ---- decoder: 24 steps ----
    #pragma unroll 1
    for (int t = 0; t < TOUT; t++) {
        const int pl = t & 1;
        kloop(gAr[pl]);                 // waits imply all flags >= t+SEQ+1
        if (t > 0 && tid < 128) {
            float o = fcb0;
            #pragma unroll
            for (int s2 = 0; s2 < 8; s2++)
                o += __ldcg(&g_part[(t - 1) & 1][g][s2][tid]);
            dinp[tid] = o;
            if (s == 0) out[(b0 + tid) * TOUT + (t - 1)] = o;
        }
        __syncthreads();
        float xa0 = dinp[r00], xb0 = dinp[r01];
        float xa1 = dinp[r10], xb1 = dinp[r11];
        epi(xa0, xb0, xa1, xb1, epD, gAw[1 - pl], true);
        __syncthreads();                // red complete
        if (tid < 128)
            g_part[t & 1][g][s][tid] = red[tid] + red[128 + tid];
        publish();                      // covers g_part[t&1] too
    }

    // ---- final output column: need all flags >= ph+1 (= 153) ----
    {
        const unsigned tgt = ph + 1;
        if (tid < 8) {
            volatile const unsigned* fp = &g_flag[g][tid][0];
            while (*fp < tgt) { }
            __threadfence();
        }
        __syncthreads();
        if (tid < 128 && s == 0) {
            float o = fcb0;
            #pragma unroll
            for (int s2 = 0; s2 < 8; s2++)
                o += __ldcg(&g_part[(TOUT - 1) & 1][g][s2][tid]);
            out[(b0 + tid) * TOUT + (TOUT - 1)] = o;
        }
    }

    // ---- reset flags for next graph replay ----
    __syncthreads();
    if (tid == 0) {
        unsigned r = atomicAdd(&g_rst[g][0], 1u);
        if (r == 7u) {
            #pragma unroll
            for (int p = 0; p < 8; p++) g_flag[g][p][0] = 0u;
            g_rst[g][0] = 0u;
            __threadfence();
        }
    }
}

extern "C" void kernel_launch(void* const* d_in, const int* in_sizes, int n_in,
                              void* d_out, int out_size) {
    (void)in_sizes; (void)n_in; (void)out_size;
    const float* x    = (const float*)d_in[0];
    const float* eWih = (const float*)d_in[1];
    const float* eWhh = (const float*)d_in[2];
    const float* ebih = (const float*)d_in[3];
    const float* ebhh = (const float*)d_in[4];
    const float* dWih = (const float*)d_in[5];
    const float* dWhh = (const float*)d_in[6];
    const float* dbih = (const float*)d_in[7];
    const float* dbhh = (const float*)d_in[8];
    const float* fcW  = (const float*)d_in[9];
    const float* fcb  = (const float*)d_in[10];

    cudaFuncSetAttribute(rnn_kernel, cudaFuncAttributeMaxDynamicSharedMemorySize, SMEM_SZ);

    pack_b<<<dim3(256, 2), 256>>>(eWhh, dWhh);
    transpose_x<<<dim3(BATCH / 32, SEQ / 32), dim3(32, 8)>>>(x);
    rnn_kernel<<<GRID, NTHR, SMEM_SZ>>>(eWih, ebih, ebhh,
                                        dWih, dbih, dbhh,
                                        fcW, fcb, (float*)d_out);
}

// round 15
// speedup vs baseline: 1.3919x; 1.3919x over previous
#include <cuda_runtime.h>
#include <cuda_bf16.h>
#include <math.h>
#include <stdint.h>

#define BATCH 2048
#define SEQ   128
#define HID   512
#define TOUT  24
#define NTHR  256    // 8 warps, one per m-tile
#define GRID  128
#define NKT   32

// ---- global scratch ----
__device__ uint4 g_A[16][2][8][NKT][2][32];  // [grp][plane][mt][kt][hi/lo][lane]
__device__ float g_xT[SEQ][BATCH];           // transposed input
__device__ float g_part[2][16][8][128];      // fc partials (parity-buffered)
__device__ unsigned g_bar[16][32];           // group barrier counters
__device__ unsigned g_rst[16][32];           // reset counters

// ---- SMEM layout (bytes) ----
#define OFF_B    0         // resident B slice: 32kt x 8ntl x 32 x 16B = 131072
#define OFF_EPE  131072    // 32 float4
#define OFF_EPD  131584    // 32 float4
#define OFF_FC2  132096    // 32 float2
#define OFF_DINP 132352    // 128 f
#define SMEM_SZ  132864

__device__ __forceinline__ void mma_bf16(float* d, uint4 a, uint32_t b0, uint32_t b1) {
    asm volatile(
        "mma.sync.aligned.m16n8k16.row.col.f32.bf16.bf16.f32 "
        "{%0,%1,%2,%3}, {%4,%5,%6,%7}, {%8,%9}, {%0,%1,%2,%3};"
        : "+f"(d[0]), "+f"(d[1]), "+f"(d[2]), "+f"(d[3])
        : "r"(a.x), "r"(a.y), "r"(a.z), "r"(a.w), "r"(b0), "r"(b1));
}
__device__ __forceinline__ uint32_t pack_bf2(__nv_bfloat16 a, __nv_bfloat16 b) {
    __nv_bfloat162 t; t.x = a; t.y = b;
    return *reinterpret_cast<uint32_t*>(&t);
}
__device__ __forceinline__ void split2(float a, float b, uint32_t& hi, uint32_t& lo) {
    __nv_bfloat16 ah = __float2bfloat16(a);
    __nv_bfloat16 bh = __float2bfloat16(b);
    __nv_bfloat16 al = __float2bfloat16(a - __bfloat162float(ah));
    __nv_bfloat16 bl = __float2bfloat16(b - __bfloat162float(bh));
    hi = pack_bf2(ah, bh);
    lo = pack_bf2(al, bl);
}
// fast tanh on MUFU pipe: abs err ~2^-20, far below the 3x-bf16 error floor
__device__ __forceinline__ float ftanh(float x) {
    float e = __expf(2.0f * x);
    return 1.0f - __fdividef(2.0f, e + 1.0f);
}

// Prologue: transpose x -> g_xT[s][b].
__global__ void transpose_x(const float* __restrict__ x) {
    __shared__ float tile[32][33];
    int bx = blockIdx.x * 32, sx = blockIdx.y * 32;
    int tx = threadIdx.x, ty = threadIdx.y;
    #pragma unroll
    for (int i = 0; i < 32; i += 8)
        tile[ty + i][tx] = x[(bx + ty + i) * SEQ + sx + tx];
    __syncthreads();
    #pragma unroll
    for (int i = 0; i < 32; i += 8)
        g_xT[sx + ty + i][bx + tx] = tile[tx][ty + i];
}

__global__ __launch_bounds__(NTHR, 1)
void rnn_kernel(const float* __restrict__ eWhh, const float* __restrict__ dWhh,
                const float* __restrict__ eWih,
                const float* __restrict__ ebih, const float* __restrict__ ebhh,
                const float* __restrict__ dWih,
                const float* __restrict__ dbih, const float* __restrict__ dbhh,
                const float* __restrict__ fcW, const float* __restrict__ fcb,
                float* __restrict__ out)
{
    extern __shared__ char smem[];
    const int tid  = threadIdx.x;
    const int wid  = tid >> 5, lane = tid & 31;
    const int gid  = lane >> 2, tig = lane & 3;
    const int g    = blockIdx.x >> 3, s = blockIdx.x & 7;
    const int b0   = g * 128, n0 = s * 64, s4 = s * 4;
    const int mt   = wid;                  // one m-tile per warp
    const int r0   = mt * 16 + gid, r1 = r0 + 8;

    const uint4* smB  = (const uint4*)(smem + OFF_B);
    uint4*       smBw = (uint4*)(smem + OFF_B);
    float4* epE  = (float4*)(smem + OFF_EPE);
    float4* epD  = (float4*)(smem + OFF_EPD);
    float2* fc2  = (float2*)(smem + OFF_FC2);
    float*  dinp = (float*)(smem + OFF_DINP);

    // ---- epilogue tables ----
    if (tid < 32) {
        int c0 = n0 + 2 * tid, c1 = c0 + 1;
        epE[tid] = make_float4(eWih[c0], eWih[c1],
                               ebih[c0] + ebhh[c0], ebih[c1] + ebhh[c1]);
        epD[tid] = make_float4(dWih[c0], dWih[c1],
                               dbih[c0] + dbhh[c0], dbih[c1] + dbhh[c1]);
        fc2[tid] = make_float2(fcW[c0], fcW[c1]);
    }
    const float fcb0 = fcb[0];

    // ---- pack this CTA's 64-col Whh slice into fragment-ordered bf16 hi/lo ----
    // entry e = kt*256 + ntl*32 + lane2 -> n = n0 + ntl*8 + (lane2>>2),
    // k = kt*16 + 2*(lane2&3); uint4 {b0h, b1h, b0l, b1l}  (layout proven R8-R13)
    auto packB = [&](const float* __restrict__ W) {
        #pragma unroll 1
        for (int i = 0; i < 32; i++) {
            int e = tid + i * NTHR;
            int lane2 = e & 31, ntl = (e >> 5) & 7, kt = e >> 8;
            int n = n0 + ntl * 8 + (lane2 >> 2);
            int k = kt * 16 + 2 * (lane2 & 3);
            const float* r = W + n * HID + k;
            float2 a = *(const float2*)r;
            float2 b = *(const float2*)(r + 8);
            uint32_t b0h, b0l, b1h, b1l;
            split2(a.x, a.y, b0h, b0l);
            split2(b.x, b.y, b1h, b1l);
            smBw[e] = make_uint4(b0h, b1h, b0l, b1l);
        }
    };

    packB(eWhh);
    // zero own g_A plane-0 partition (h0 = 0)
    {
        uint4* az = &g_A[g][0][s][0][0][0];
        for (int i = tid; i < 2048; i += NTHR) az[i] = make_uint4(0, 0, 0, 0);
    }

    unsigned ph = 0;
    volatile unsigned* barp = &g_bar[g][0];
    auto arrive = [&]() {
        __syncthreads();
        if (tid == 0) {
            __threadfence();
            atomicAdd(&g_bar[g][0], 1u);
        }
    };
    auto wait_flag = [&]() {
        ph++;
        const unsigned tgt = 8u * ph;
        if (lane == 0) {
            while (*barp < tgt) { }
            __threadfence();
        }
        __syncwarp();
    };

    arrive();   // publish zeros (and ensure smB pack is done CTA-wide)

    // Own h fragments live in registers across steps (h0 = 0).
    uint4 own_h[4], own_l[4];
    #pragma unroll
    for (int i = 0; i < 4; i++) {
        own_h[i] = make_uint4(0, 0, 0, 0);
        own_l[i] = make_uint4(0, 0, 0, 0);
    }

    float acc[8][4];

    // consume one k-tile: 8 n-tiles x 3 terms; acc-interleaved for MMA ILP.
    auto consume = [&](int kt, uint4 ah, uint4 al) {
        const uint4* bp = smB + kt * 256 + lane;
        uint4 b0 = bp[0],   b1 = bp[32],  b2 = bp[64],  b3 = bp[96];
        uint4 b4 = bp[128], b5 = bp[160], b6 = bp[192], b7 = bp[224];
        mma_bf16(acc[0], ah, b0.x, b0.y); mma_bf16(acc[1], ah, b1.x, b1.y);
        mma_bf16(acc[2], ah, b2.x, b2.y); mma_bf16(acc[3], ah, b3.x, b3.y);
        mma_bf16(acc[4], ah, b4.x, b4.y); mma_bf16(acc[5], ah, b5.x, b5.y);
        mma_bf16(acc[6], ah, b6.x, b6.y); mma_bf16(acc[7], ah, b7.x, b7.y);
        mma_bf16(acc[0], al, b0.x, b0.y); mma_bf16(acc[1], al, b1.x, b1.y);
        mma_bf16(acc[2], al, b2.x, b2.y); mma_bf16(acc[3], al, b3.x, b3.y);
        mma_bf16(acc[4], al, b4.x, b4.y); mma_bf16(acc[5], al, b5.x, b5.y);
        mma_bf16(acc[6], al, b6.x, b6.y); mma_bf16(acc[7], al, b7.x, b7.y);
        mma_bf16(acc[0], ah, b0.z, b0.w); mma_bf16(acc[1], ah, b1.z, b1.w);
        mma_bf16(acc[2], ah, b2.z, b2.w); mma_bf16(acc[3], ah, b3.z, b3.w);
        mma_bf16(acc[4], ah, b4.z, b4.w); mma_bf16(acc[5], ah, b5.z, b5.w);
        mma_bf16(acc[6], ah, b6.z, b6.w); mma_bf16(acc[7], ah, b7.z, b7.w);
    };

    // kloop: own 4 tiles from regs (overlaps the barrier), then 28 foreign
    // tiles via depth-4 __ldcg register pipeline (L1-bypass: planes recycle).
    auto kloop = [&](const uint4* __restrict__ base) {
        #pragma unroll
        for (int i = 0; i < 8; i++)
            #pragma unroll
            for (int j = 0; j < 4; j++) acc[i][j] = 0.f;
        consume(s4 + 0, own_h[0], own_l[0]);
        consume(s4 + 1, own_h[1], own_l[1]);
        consume(s4 + 2, own_h[2], own_l[2]);
        consume(s4 + 3, own_h[3], own_l[3]);
        wait_flag();
        uint4 ph_[4], pl_[4];
        #pragma unroll
        for (int u = 0; u < 4; u++) {
            int kt = (s4 + 4 + u) & 31;
            ph_[u] = __ldcg(base + kt * 64 + lane);
            pl_[u] = __ldcg(base + kt * 64 + 32 + lane);
        }
        #pragma unroll 1
        for (int j = 0; j < 6; j++) {
            #pragma unroll
            for (int u = 0; u < 4; u++) {
                int idx = 4 + j * 4 + u;
                int kt = (s4 + idx) & 31;
                uint4 ah = ph_[u], al = pl_[u];
                int nk = (s4 + idx + 4) & 31;
                ph_[u] = __ldcg(base + nk * 64 + lane);
                pl_[u] = __ldcg(base + nk * 64 + 32 + lane);
                consume(kt, ah, al);
            }
        }
        #pragma unroll
        for (int u = 0; u < 4; u++)
            consume((s4 + 28 + u) & 31, ph_[u], pl_[u]);
    };

    // epilogue: h = ftanh(acc + xv*wih + bias); own fragments -> regs + g_A.
    auto epi = [&](float xv0, float xv1, const float4* __restrict__ ep,
                   uint4* __restrict__ gAw, bool dec, int par) {
        float p0 = 0.f, p1 = 0.f;
        uint4 nh_[4], nl_[4];
        #pragma unroll
        for (int i = 0; i < 8; i++) {
            int pp = 4 * i + tig;
            float4 co = ep[pp];
            float h00 = ftanh(acc[i][0] + xv0 * co.x + co.z);
            float h01 = ftanh(acc[i][1] + xv0 * co.y + co.w);
            float h10 = ftanh(acc[i][2] + xv1 * co.x + co.z);
            float h11 = ftanh(acc[i][3] + xv1 * co.y + co.w);
            if (dec) {
                float2 f = fc2[pp];
                p0 = fmaf(h00, f.x, fmaf(h01, f.y, p0));
                p1 = fmaf(h10, f.x, fmaf(h11, f.y, p1));
            }
            int ktl = i >> 1;
            if ((i & 1) == 0) {
                split2(h00, h01, nh_[ktl].x, nl_[ktl].x);
                split2(h10, h11, nh_[ktl].y, nl_[ktl].y);
            } else {
                split2(h00, h01, nh_[ktl].z, nl_[ktl].z);
                split2(h10, h11, nh_[ktl].w, nl_[ktl].w);
            }
        }
        #pragma unroll
        for (int ktl = 0; ktl < 4; ktl++) {
            own_h[ktl] = nh_[ktl];
            own_l[ktl] = nl_[ktl];
            int kt = s4 + ktl;
            gAw[kt * 64 + lane]      = nh_[ktl];
            gAw[kt * 64 + 32 + lane] = nl_[ktl];
        }
        if (dec) {
            p0 += __shfl_xor_sync(0xffffffffu, p0, 1);
            p0 += __shfl_xor_sync(0xffffffffu, p0, 2);
            p1 += __shfl_xor_sync(0xffffffffu, p1, 1);
            p1 += __shfl_xor_sync(0xffffffffu, p1, 2);
            if (tig == 0) {
                g_part[par][g][s][r0] = p0;
                g_part[par][g][s][r1] = p1;
            }
        }
    };

    const uint4* gAr[2] = { &g_A[g][0][mt][0][0][0], &g_A[g][1][mt][0][0][0] };
    uint4*       gAw[2] = { &g_A[g][0][mt][0][0][0], &g_A[g][1][mt][0][0][0] };

    // ---- encoder: 128 steps ----
    #pragma unroll 1
    for (int t = 0; t < SEQ; t++) {
        const int pl = t & 1;
        float xv0 = __ldg(&g_xT[t][b0 + r0]);
        float xv1 = __ldg(&g_xT[t][b0 + r1]);
        kloop(gAr[pl]);
        epi(xv0, xv1, epE, gAw[1 - pl], false, 0);
        arrive();
    }

    // ---- swap to decoder B (pack in place; smB reads all done) ----
    __syncthreads();
    packB(dWhh);
    if (tid < 128) dinp[tid] = __ldg(&g_xT[SEQ - 1][b0 + tid]);
    __syncthreads();

    // ---- decoder: 24 steps ----
    #pragma unroll 1
    for (int t = 0; t < TOUT; t++) {
        const int pl = t & 1;
        kloop(gAr[pl]);                 // wait also publishes g_part of step t-1
        if (t > 0 && tid < 128) {
            float o = fcb0;
            #pragma unroll
            for (int s2 = 0; s2 < 8; s2++)
                o += __ldcg(&g_part[(t - 1) & 1][g][s2][tid]);
            dinp[tid] = o;
            if (s == 0) out[(b0 + tid) * TOUT + (t - 1)] = o;
        }
        __syncthreads();                // dinp stable before epi reads it
        float xv0 = dinp[r0];
        float xv1 = dinp[r1];
        epi(xv0, xv1, epD, gAw[1 - pl], true, t & 1);
        arrive();
    }

    // ---- final output column ----
    wait_flag();
    if (tid < 128 && s == 0) {
        float o = fcb0;
        #pragma unroll
        for (int s2 = 0; s2 < 8; s2++)
            o += __ldcg(&g_part[(TOUT - 1) & 1][g][s2][tid]);
        out[(b0 + tid) * TOUT + (TOUT - 1)] = o;
    }

    // ---- reset barrier counters for next graph replay ----
    __syncthreads();
    if (tid == 0) {
        unsigned r = atomicAdd(&g_rst[g][0], 1u);
        if (r == 7u) {
            g_bar[g][0] = 0u;
            g_rst[g][0] = 0u;
            __threadfence();
        }
    }
}

extern "C" void kernel_launch(void* const* d_in, const int* in_sizes, int n_in,
                              void* d_out, int out_size) {
    (void)in_sizes; (void)n_in; (void)out_size;
    const float* x    = (const float*)d_in[0];
    const float* eWih = (const float*)d_in[1];
    const float* eWhh = (const float*)d_in[2];
    const float* ebih = (const float*)d_in[3];
    const float* ebhh = (const float*)d_in[4];
    const float* dWih = (const float*)d_in[5];
    const float* dWhh = (const float*)d_in[6];
    const float* dbih = (const float*)d_in[7];
    const float* dbhh = (const float*)d_in[8];
    const float* fcW  = (const float*)d_in[9];
    const float* fcb  = (const float*)d_in[10];

    cudaFuncSetAttribute(rnn_kernel, cudaFuncAttributeMaxDynamicSharedMemorySize, SMEM_SZ);

    transpose_x<<<dim3(BATCH / 32, SEQ / 32), dim3(32, 8)>>>(x);
    rnn_kernel<<<GRID, NTHR, SMEM_SZ>>>(eWhh, dWhh, eWih, ebih, ebhh,
                                        dWih, dbih, dbhh,
                                        fcW, fcb, (float*)d_out);
}

// round 16
// speedup vs baseline: 1.4026x; 1.0077x over previous
#include <cuda_runtime.h>
#include <cuda_bf16.h>
#include <math.h>
#include <stdint.h>

#define BATCH 2048
#define SEQ   128
#define HID   512
#define TOUT  24
#define NTHR  512    // 16 warps: 8 m-tiles x 2 n-halves
#define GRID  128
#define NKT   32

// ---- global scratch ----
__device__ uint4 g_A[16][2][8][NKT][2][32];  // [grp][plane][mt][kt][hi/lo][lane]
__device__ float g_xT[SEQ][BATCH];           // transposed input
__device__ float g_part[2][16][8][128];      // fc partials (parity-buffered)
__device__ unsigned g_bar[16][32];           // group barrier counters
__device__ unsigned g_rst[16][32];           // reset counters

// ---- SMEM layout (bytes) ----
#define OFF_B    0         // resident B slice: 32kt x 8ntl x 32 x 16B = 131072
#define OFF_EPE  131072    // 32 float4
#define OFF_EPD  131584    // 32 float4
#define OFF_FC2  132096    // 32 float2
#define OFF_DINP 132352    // 128 f
#define OFF_RED  132864    // 2 x 128 f
#define SMEM_SZ  133888

__device__ __forceinline__ void mma_bf16(float* d, uint4 a, uint32_t b0, uint32_t b1) {
    asm volatile(
        "mma.sync.aligned.m16n8k16.row.col.f32.bf16.bf16.f32 "
        "{%0,%1,%2,%3}, {%4,%5,%6,%7}, {%8,%9}, {%0,%1,%2,%3};"
        : "+f"(d[0]), "+f"(d[1]), "+f"(d[2]), "+f"(d[3])
        : "r"(a.x), "r"(a.y), "r"(a.z), "r"(a.w), "r"(b0), "r"(b1));
}
__device__ __forceinline__ uint32_t pack_bf2(__nv_bfloat16 a, __nv_bfloat16 b) {
    __nv_bfloat162 t; t.x = a; t.y = b;
    return *reinterpret_cast<uint32_t*>(&t);
}
__device__ __forceinline__ void split2(float a, float b, uint32_t& hi, uint32_t& lo) {
    __nv_bfloat16 ah = __float2bfloat16(a);
    __nv_bfloat16 bh = __float2bfloat16(b);
    __nv_bfloat16 al = __float2bfloat16(a - __bfloat162float(ah));
    __nv_bfloat16 bl = __float2bfloat16(b - __bfloat162float(bh));
    hi = pack_bf2(ah, bh);
    lo = pack_bf2(al, bl);
}
// fast tanh on MUFU pipe: abs err ~2^-20, far below the 3x-bf16 error floor
__device__ __forceinline__ float ftanh(float x) {
    float e = __expf(2.0f * x);
    return 1.0f - __fdividef(2.0f, e + 1.0f);
}

// Prologue: transpose x -> g_xT[s][b].
__global__ void transpose_x(const float* __restrict__ x) {
    __shared__ float tile[32][33];
    int bx = blockIdx.x * 32, sx = blockIdx.y * 32;
    int tx = threadIdx.x, ty = threadIdx.y;
    #pragma unroll
    for (int i = 0; i < 32; i += 8)
        tile[ty + i][tx] = x[(bx + ty + i) * SEQ + sx + tx];
    __syncthreads();
    #pragma unroll
    for (int i = 0; i < 32; i += 8)
        g_xT[sx + ty + i][bx + tx] = tile[tx][ty + i];
}

__global__ __launch_bounds__(NTHR, 1)
void rnn_kernel(const float* __restrict__ eWhh, const float* __restrict__ dWhh,
                const float* __restrict__ eWih,
                const float* __restrict__ ebih, const float* __restrict__ ebhh,
                const float* __restrict__ dWih,
                const float* __restrict__ dbih, const float* __restrict__ dbhh,
                const float* __restrict__ fcW, const float* __restrict__ fcb,
                float* __restrict__ out)
{
    extern __shared__ char smem[];
    const int tid  = threadIdx.x;
    const int wid  = tid >> 5, lane = tid & 31;
    const int gid  = lane >> 2, tig = lane & 3;
    const int g    = blockIdx.x >> 3, s = blockIdx.x & 7;
    const int b0   = g * 128, n0 = s * 64, s4 = s * 4;
    const int mt   = wid & 7, nhf = wid >> 3;
    const int r0   = mt * 16 + gid, r1 = r0 + 8;

    const uint4* smB  = (const uint4*)(smem + OFF_B);
    uint4*       smBw = (uint4*)(smem + OFF_B);
    float4* epE  = (float4*)(smem + OFF_EPE);
    float4* epD  = (float4*)(smem + OFF_EPD);
    float2* fc2  = (float2*)(smem + OFF_FC2);
    float*  dinp = (float*)(smem + OFF_DINP);
    float*  red  = (float*)(smem + OFF_RED);

    // ---- epilogue tables ----
    if (tid < 32) {
        int c0 = n0 + 2 * tid, c1 = c0 + 1;
        epE[tid] = make_float4(eWih[c0], eWih[c1],
                               ebih[c0] + ebhh[c0], ebih[c1] + ebhh[c1]);
        epD[tid] = make_float4(dWih[c0], dWih[c1],
                               dbih[c0] + dbhh[c0], dbih[c1] + dbhh[c1]);
        fc2[tid] = make_float2(fcW[c0], fcW[c1]);
    }
    const float fcb0 = fcb[0];

    // ---- pack this CTA's 64-col Whh slice into fragment-ordered bf16 hi/lo ----
    auto packB = [&](const float* __restrict__ W) {
        #pragma unroll 1
        for (int i = 0; i < 16; i++) {
            int e = tid + i * NTHR;
            int lane2 = e & 31, ntl = (e >> 5) & 7, kt = e >> 8;
            int n = n0 + ntl * 8 + (lane2 >> 2);
            int k = kt * 16 + 2 * (lane2 & 3);
            const float* r = W + n * HID + k;
            float2 a = *(const float2*)r;
            float2 b = *(const float2*)(r + 8);
            uint32_t b0h, b0l, b1h, b1l;
            split2(a.x, a.y, b0h, b0l);
            split2(b.x, b.y, b1h, b1l);
            smBw[e] = make_uint4(b0h, b1h, b0l, b1l);
        }
    };

    packB(eWhh);
    // zero own g_A plane-0 partition (h0 = 0)
    {
        uint4* az = &g_A[g][0][s][0][0][0];
        for (int i = tid; i < 2048; i += NTHR) az[i] = make_uint4(0, 0, 0, 0);
    }

    unsigned ph = 0;
    volatile unsigned* barp = &g_bar[g][0];
    auto arrive = [&]() {
        __syncthreads();
        if (tid == 0) {
            __threadfence();
            atomicAdd(&g_bar[g][0], 1u);
        }
    };
    auto wait_flag = [&]() {
        ph++;
        const unsigned tgt = 8u * ph;
        if (lane == 0) {
            while (*barp < tgt) { }
            __threadfence();
        }
        __syncwarp();
    };

    arrive();   // publish zeros (and ensure smB pack done CTA-wide)

    // Own h fragments (this warp's 2 k-tiles: ktl = nhf*2 + {0,1}) in registers.
    uint4 own_h[2], own_l[2];
    #pragma unroll
    for (int i = 0; i < 2; i++) {
        own_h[i] = make_uint4(0, 0, 0, 0);
        own_l[i] = make_uint4(0, 0, 0, 0);
    }

    float acc[4][4];

    // consume one k-tile: 4 n-tiles (this warp's half) x 3 terms.
    auto consume = [&](int kt, uint4 ah, uint4 al) {
        const uint4* bp = smB + kt * 256 + nhf * 128 + lane;
        uint4 b0 = bp[0], b1 = bp[32], b2 = bp[64], b3 = bp[96];
        mma_bf16(acc[0], ah, b0.x, b0.y); mma_bf16(acc[1], ah, b1.x, b1.y);
        mma_bf16(acc[2], ah, b2.x, b2.y); mma_bf16(acc[3], ah, b3.x, b3.y);
        mma_bf16(acc[0], al, b0.x, b0.y); mma_bf16(acc[1], al, b1.x, b1.y);
        mma_bf16(acc[2], al, b2.x, b2.y); mma_bf16(acc[3], al, b3.x, b3.y);
        mma_bf16(acc[0], ah, b0.z, b0.w); mma_bf16(acc[1], ah, b1.z, b1.w);
        mma_bf16(acc[2], ah, b2.z, b2.w); mma_bf16(acc[3], ah, b3.z, b3.w);
    };

    // kloop: 2 own kt from regs + 2 partner kt via __ldcg (intra-CTA, ordered
    // by arrive's syncthreads) overlap the barrier; then 28 foreign kt via
    // depth-4 __ldcg register pipeline (L1 bypass: planes recycle).
    auto kloop = [&](const uint4* __restrict__ base) {
        #pragma unroll
        for (int i = 0; i < 4; i++)
            #pragma unroll
            for (int j = 0; j < 4; j++) acc[i][j] = 0.f;
        const int ko = s4 + nhf * 2;            // own kt base
        const int kp = s4 + (1 - nhf) * 2;      // partner kt base
        uint4 qh0 = __ldcg(base + kp * 64 + lane);
        uint4 ql0 = __ldcg(base + kp * 64 + 32 + lane);
        uint4 qh1 = __ldcg(base + (kp + 1) * 64 + lane);
        uint4 ql1 = __ldcg(base + (kp + 1) * 64 + 32 + lane);
        consume(ko,     own_h[0], own_l[0]);
        consume(ko + 1, own_h[1], own_l[1]);
        consume(kp,     qh0, ql0);
        consume(kp + 1, qh1, ql1);
        wait_flag();
        uint4 ph_[4], pl_[4];
        #pragma unroll
        for (int u = 0; u < 4; u++) {
            int kt = (s4 + 4 + u) & 31;
            ph_[u] = __ldcg(base + kt * 64 + lane);
            pl_[u] = __ldcg(base + kt * 64 + 32 + lane);
        }
        #pragma unroll 1
        for (int j = 0; j < 6; j++) {
            #pragma unroll
            for (int u = 0; u < 4; u++) {
                int idx = 4 + j * 4 + u;
                int kt = (s4 + idx) & 31;
                uint4 ah = ph_[u], al = pl_[u];
                int nk = (s4 + idx + 4) & 31;
                ph_[u] = __ldcg(base + nk * 64 + lane);
                pl_[u] = __ldcg(base + nk * 64 + 32 + lane);
                consume(kt, ah, al);
            }
        }
        #pragma unroll
        for (int u = 0; u < 4; u++)
            consume((s4 + 28 + u) & 31, ph_[u], pl_[u]);
    };

    // epilogue: h = ftanh(acc + xv*wih + bias); own 2 kt -> regs + g_A.
    auto epi = [&](float xv0, float xv1, const float4* __restrict__ ep,
                   uint4* __restrict__ gAw, bool dec) {
        float p0 = 0.f, p1 = 0.f;
        uint4 nh_[2], nl_[2];
        #pragma unroll
        for (int j = 0; j < 4; j++) {
            int pp = 16 * nhf + 4 * j + tig;
            float4 co = ep[pp];
            float h00 = ftanh(acc[j][0] + xv0 * co.x + co.z);
            float h01 = ftanh(acc[j][1] + xv0 * co.y + co.w);
            float h10 = ftanh(acc[j][2] + xv1 * co.x + co.z);
            float h11 = ftanh(acc[j][3] + xv1 * co.y + co.w);
            if (dec) {
                float2 f = fc2[pp];
                p0 = fmaf(h00, f.x, fmaf(h01, f.y, p0));
                p1 = fmaf(h10, f.x, fmaf(h11, f.y, p1));
            }
            int ktl = j >> 1;
            if ((j & 1) == 0) {
                split2(h00, h01, nh_[ktl].x, nl_[ktl].x);
                split2(h10, h11, nh_[ktl].y, nl_[ktl].y);
            } else {
                split2(h00, h01, nh_[ktl].z, nl_[ktl].z);
                split2(h10, h11, nh_[ktl].w, nl_[ktl].w);
            }
        }
        #pragma unroll
        for (int ktl = 0; ktl < 2; ktl++) {
            own_h[ktl] = nh_[ktl];
            own_l[ktl] = nl_[ktl];
            int kt = s4 + nhf * 2 + ktl;
            gAw[kt * 64 + lane]      = nh_[ktl];
            gAw[kt * 64 + 32 + lane] = nl_[ktl];
        }
        if (dec) {
            p0 += __shfl_xor_sync(0xffffffffu, p0, 1);
            p0 += __shfl_xor_sync(0xffffffffu, p0, 2);
            p1 += __shfl_xor_sync(0xffffffffu, p1, 1);
            p1 += __shfl_xor_sync(0xffffffffu, p1, 2);
            if (tig == 0) {
                red[nhf * 128 + r0] = p0;
                red[nhf * 128 + r1] = p1;
            }
        }
    };

    const uint4* gAr[2] = { &g_A[g][0][mt][0][0][0], &g_A[g][1][mt][0][0][0] };
    uint4*       gAw[2] = { &g_A[g][0][mt][0][0][0], &g_A[g][1][mt][0][0][0] };

    // ---- encoder: 128 steps ----
    #pragma unroll 1
    for (int t = 0; t < SEQ; t++) {
        const int pl = t & 1;
        float xv0 = __ldg(&g_xT[t][b0 + r0]);
        float xv1 = __ldg(&g_xT[t][b0 + r1]);
        kloop(gAr[pl]);
        epi(xv0, xv1, epE, gAw[1 - pl], false);
        arrive();
    }

    // ---- swap to decoder B (pack in place; smB reads all done) ----
    __syncthreads();
    packB(dWhh);
    if (tid < 128) dinp[tid] = __ldg(&g_xT[SEQ - 1][b0 + tid]);
    __syncthreads();

    // ---- decoder: 24 steps ----
    #pragma unroll 1
    for (int t = 0; t < TOUT; t++) {
        const int pl = t & 1;
        kloop(gAr[pl]);                 // wait also publishes g_part of step t-1
        if (t > 0 && tid < 128) {
            float o = fcb0;
            #pragma unroll
            for (int s2 = 0; s2 < 8; s2++)
                o += __ldcg(&g_part[(t - 1) & 1][g][s2][tid]);
            dinp[tid] = o;
            if (s == 0) out[(b0 + tid) * TOUT + (t - 1)] = o;
        }
        __syncthreads();                // dinp stable before epi reads it
        float xv0 = dinp[r0];
        float xv1 = dinp[r1];
        epi(xv0, xv1, epD, gAw[1 - pl], true);
        __syncthreads();                // red complete (both n-halves)
        if (tid < 128)
            g_part[t & 1][g][s][tid] = red[tid] + red[128 + tid];
        arrive();
    }

    // ---- final output column ----
    wait_flag();
    if (tid < 128 && s == 0) {
        float o = fcb0;
        #pragma unroll
        for (int s2 = 0; s2 < 8; s2++)
            o += __ldcg(&g_part[(TOUT - 1) & 1][g][s2][tid]);
        out[(b0 + tid) * TOUT + (TOUT - 1)] = o;
    }

    // ---- reset barrier counters for next graph replay ----
    __syncthreads();
    if (tid == 0) {
        unsigned r = atomicAdd(&g_rst[g][0], 1u);
        if (r == 7u) {
            g_bar[g][0] = 0u;
            g_rst[g][0] = 0u;
            __threadfence();
        }
    }
}

extern "C" void kernel_launch(void* const* d_in, const int* in_sizes, int n_in,
                              void* d_out, int out_size) {
    (void)in_sizes; (void)n_in; (void)out_size;
    const float* x    = (const float*)d_in[0];
    const float* eWih = (const float*)d_in[1];
    const float* eWhh = (const float*)d_in[2];
    const float* ebih = (const float*)d_in[3];
    const float* ebhh = (const float*)d_in[4];
    const float* dWih = (const float*)d_in[5];
    const float* dWhh = (const float*)d_in[6];
    const float* dbih = (const float*)d_in[7];
    const float* dbhh = (const float*)d_in[8];
    const float* fcW  = (const float*)d_in[9];
    const float* fcb  = (const float*)d_in[10];

    cudaFuncSetAttribute(rnn_kernel, cudaFuncAttributeMaxDynamicSharedMemorySize, SMEM_SZ);

    transpose_x<<<dim3(BATCH / 32, SEQ / 32), dim3(32, 8)>>>(x);
    rnn_kernel<<<GRID, NTHR, SMEM_SZ>>>(eWhh, dWhh, eWih, ebih, ebhh,
                                        dWih, dbih, dbhh,
                                        fcW, fcb, (float*)d_out);
}